// round 2
// baseline (speedup 1.0000x reference)
#include <cuda_runtime.h>
#include <cuda_bf16.h>
#include <cstdint>

// Problem shape (fixed by reference setup_inputs): x [B=64, C=1, H=64, W=2048] f32
#define H_DIM 64
#define W_DIM 2048

// exp(-0.5 * sqrt(2)) and exp(-0.5)
#define W_CORNER 0.4930686913952603f
#define W_CENTER 0.6065306597126334f

__device__ unsigned g_min_key;

__device__ __forceinline__ unsigned fkey(float f) {
    unsigned u = __float_as_uint(f);
    return (u & 0x80000000u) ? ~u : (u | 0x80000000u);
}
__device__ __forceinline__ float fdecode(unsigned k) {
    return __uint_as_float((k & 0x80000000u) ? (k ^ 0x80000000u) : ~k);
}

__global__ void min_init_kernel() {
    // key(0.0f): padded zeros participate in the global window min
    g_min_key = 0x80000000u;
}

__global__ void __launch_bounds__(256) min_reduce_kernel(const float* __restrict__ x, int n4) {
    int gid = blockIdx.x * blockDim.x + threadIdx.x;
    int stride = gridDim.x * blockDim.x;
    float m = 3.4e38f;
    const float4* __restrict__ x4 = reinterpret_cast<const float4*>(x);
    for (int i = gid; i < n4; i += stride) {
        float4 v = __ldg(x4 + i);
        m = fminf(m, fminf(fminf(v.x, v.y), fminf(v.z, v.w)));
    }
    // warp reduce
    #pragma unroll
    for (int off = 16; off > 0; off >>= 1)
        m = fminf(m, __shfl_xor_sync(0xFFFFFFFFu, m, off));
    __shared__ float sm[8];
    int lane = threadIdx.x & 31;
    int wid = threadIdx.x >> 5;
    if (lane == 0) sm[wid] = m;
    __syncthreads();
    if (wid == 0) {
        m = (lane < (blockDim.x >> 5)) ? sm[lane] : 3.4e38f;
        #pragma unroll
        for (int off = 4; off > 0; off >>= 1)
            m = fminf(m, __shfl_xor_sync(0xFFFFFFFFu, m, off));
        if (lane == 0) atomicMin(&g_min_key, fkey(m));
    }
}

__device__ __forceinline__ void acc_one(float v, float dw, float gmin,
                                        float& num, float& den) {
    if (v != 0.0f) {
        float wi = dw * 2.0f / (1.0f + __expf(v - gmin));
        num += v * wi;
        den += wi;
    }
}

__device__ __forceinline__ float pixel6(float tl, float tc, float tr,
                                        float bl, float bc, float br,
                                        float gmin) {
    float num = 0.0f, den = 0.0f;
    acc_one(tl, W_CORNER, gmin, num, den);
    acc_one(tc, W_CENTER, gmin, num, den);
    acc_one(tr, W_CORNER, gmin, num, den);
    acc_one(bl, W_CORNER, gmin, num, den);
    acc_one(bc, W_CENTER, gmin, num, den);
    acc_one(br, W_CORNER, gmin, num, den);
    return num / ((den == 0.0f) ? 1.0f : den);
}

// grid: (W/(256*4), H, B), block: 256. Each thread owns 4 contiguous w.
__global__ void __launch_bounds__(256) upsample_conv_kernel(const float* __restrict__ x,
                                                            float* __restrict__ out) {
    const int w4 = (blockIdx.x * blockDim.x + threadIdx.x) * 4;
    const int h = blockIdx.y;
    const int b = blockIdx.z;

    const float* __restrict__ rowT = x + ((long)b * H_DIM + h) * W_DIM;
    float4 t = __ldg(reinterpret_cast<const float4*>(rowT + w4));

    float* outE = out + ((long)b * 2 * H_DIM + 2 * h) * W_DIM + w4;  // even row = copy of x row h
    float* outO = outE + W_DIM;                                      // odd row

    // even row is always a copy of x
    *reinterpret_cast<float4*>(outE) = t;

    if (h == H_DIM - 1) {
        // last odd row duplicates the last x row
        *reinterpret_cast<float4*>(outO) = t;
        return;
    }

    const float gmin = fdecode(g_min_key);

    const float* __restrict__ rowB = rowT + W_DIM;
    float4 bt = __ldg(reinterpret_cast<const float4*>(rowB + w4));

    // edge neighbors (width padded with zeros, which the mask kills)
    float tl = (w4 > 0) ? __ldg(rowT + w4 - 1) : 0.0f;
    float tr = (w4 + 4 < W_DIM) ? __ldg(rowT + w4 + 4) : 0.0f;
    float bl = (w4 > 0) ? __ldg(rowB + w4 - 1) : 0.0f;
    float br = (w4 + 4 < W_DIM) ? __ldg(rowB + w4 + 4) : 0.0f;

    float4 p;
    p.x = pixel6(tl,  t.x, t.y,  bl,  bt.x, bt.y, gmin);
    p.y = pixel6(t.x, t.y, t.z,  bt.x, bt.y, bt.z, gmin);
    p.z = pixel6(t.y, t.z, t.w,  bt.y, bt.z, bt.w, gmin);
    p.w = pixel6(t.z, t.w, tr,   bt.z, bt.w, br,  gmin);

    *reinterpret_cast<float4*>(outO) = p;
}

extern "C" void kernel_launch(void* const* d_in, const int* in_sizes, int n_in,
                              void* d_out, int out_size) {
    const float* x = (const float*)d_in[0];
    float* out = (float*)d_out;

    const int n = in_sizes[0];
    const int B = n / (H_DIM * W_DIM);

    min_init_kernel<<<1, 1>>>();
    min_reduce_kernel<<<1024, 256>>>(x, n / 4);

    dim3 grid(W_DIM / (256 * 4), H_DIM, B);
    upsample_conv_kernel<<<grid, 256>>>(x, out);
}

// round 5
// speedup vs baseline: 1.8246x; 1.8246x over previous
#include <cuda_runtime.h>
#include <cuda_bf16.h>
#include <cstdint>

// Fixed problem shape: x [B=64, C=1, H=64, W=2048] f32
#define H_DIM 64
#define W_DIM 2048
#define NBLK_MIN 1024

// 2*exp(-0.5*sqrt(2)) and 2*exp(-0.5)  (the 2x from the sigmoid folded into weights)
#define WX2 0.9861373827905206f
#define WC2 1.2130613194252668f

__device__ __align__(16) float g_blockmin[NBLK_MIN];

// ---------------- Pass 1: per-block minima (plain stores, no init needed) ---------
__global__ void __launch_bounds__(256) min_reduce_kernel(const float* __restrict__ x, int n4) {
    int gid = blockIdx.x * blockDim.x + threadIdx.x;
    int stride = gridDim.x * blockDim.x;
    float m = 3.4e38f;
    const float4* __restrict__ x4 = reinterpret_cast<const float4*>(x);
    for (int i = gid; i < n4; i += stride) {
        float4 v = __ldg(x4 + i);
        m = fminf(m, fminf(fminf(v.x, v.y), fminf(v.z, v.w)));
    }
    #pragma unroll
    for (int off = 16; off > 0; off >>= 1)
        m = fminf(m, __shfl_xor_sync(0xFFFFFFFFu, m, off));
    __shared__ float sm[8];
    int lane = threadIdx.x & 31;
    int wid = threadIdx.x >> 5;
    if (lane == 0) sm[wid] = m;
    __syncthreads();
    if (wid == 0) {
        m = (lane < 8) ? sm[lane] : 3.4e38f;
        #pragma unroll
        for (int off = 4; off > 0; off >>= 1)
            m = fminf(m, __shfl_xor_sync(0xFFFFFFFFu, m, off));
        if (lane == 0) g_blockmin[blockIdx.x] = m;
    }
}

// ---------------- Pass 2: fused scratch-reduce + copy + pixel compute -------------
// grid: (H, B), block 256, each thread owns 8 contiguous columns.
__global__ void __launch_bounds__(256) upsample_conv_kernel(const float* __restrict__ x,
                                                            float* __restrict__ out) {
    __shared__ float s_gmin;
    __shared__ float sm[8];
    const int tid = threadIdx.x;

    // Reduce the 1024 block-minima (L2-hot, 4KB) + padded zeros -> gmin
    {
        float4 v = *reinterpret_cast<const float4*>(g_blockmin + tid * 4);
        float m = fminf(fminf(v.x, v.y), fminf(v.z, v.w));
        #pragma unroll
        for (int off = 16; off > 0; off >>= 1)
            m = fminf(m, __shfl_xor_sync(0xFFFFFFFFu, m, off));
        int lane = tid & 31, wid = tid >> 5;
        if (lane == 0) sm[wid] = m;
        __syncthreads();
        if (tid == 0) {
            m = sm[0];
            #pragma unroll
            for (int i = 1; i < 8; i++) m = fminf(m, sm[i]);
            s_gmin = fminf(m, 0.0f);   // padded zeros participate in the global min
        }
        __syncthreads();
    }
    const float gmin = s_gmin;

    const int h = blockIdx.x;
    const int b = blockIdx.y;
    const int c0 = tid * 8;

    const float* __restrict__ rowT = x + ((long)b * H_DIM + h) * W_DIM;
    float4 t0 = __ldg(reinterpret_cast<const float4*>(rowT + c0));
    float4 t1 = __ldg(reinterpret_cast<const float4*>(rowT + c0 + 4));

    float* outE = out + ((long)b * 2 * H_DIM + 2 * h) * W_DIM + c0;
    float* outO = outE + W_DIM;

    // even output row = copy of x row h
    *reinterpret_cast<float4*>(outE)     = t0;
    *reinterpret_cast<float4*>(outE + 4) = t1;

    if (h == H_DIM - 1) {   // block-uniform branch
        *reinterpret_cast<float4*>(outO)     = t0;
        *reinterpret_cast<float4*>(outO + 4) = t1;
        return;
    }

    const float* __restrict__ rowB = rowT + W_DIM;
    float4 b0 = __ldg(reinterpret_cast<const float4*>(rowB + c0));
    float4 b1 = __ldg(reinterpret_cast<const float4*>(rowB + c0 + 4));

    // horizontal edge neighbors (width-padded zeros are killed by the mask)
    float tl = (c0 > 0) ? __ldg(rowT + c0 - 1) : 0.0f;
    float tr = (c0 + 8 < W_DIM) ? __ldg(rowT + c0 + 8) : 0.0f;
    float bl = (c0 > 0) ? __ldg(rowB + c0 - 1) : 0.0f;
    float br = (c0 + 8 < W_DIM) ? __ldg(rowB + c0 + 8) : 0.0f;

    float et[10] = {tl, t0.x, t0.y, t0.z, t0.w, t1.x, t1.y, t1.z, t1.w, tr};
    float eb[10] = {bl, b0.x, b0.y, b0.z, b0.w, b1.x, b1.y, b1.z, b1.w, br};

    // per-element sigmoid computed ONCE, reused by the 3 pixels that touch it
    float qt[10], pt[10], qb[10], pb[10];
    #pragma unroll
    for (int i = 0; i < 10; i++) {
        float v = et[i];
        float q = (v != 0.0f) ? __fdividef(1.0f, 1.0f + __expf(v - gmin)) : 0.0f;
        qt[i] = q; pt[i] = v * q;
        v = eb[i];
        q = (v != 0.0f) ? __fdividef(1.0f, 1.0f + __expf(v - gmin)) : 0.0f;
        qb[i] = q; pb[i] = v * q;
    }

    float r[8];
    #pragma unroll
    for (int j = 0; j < 8; j++) {
        float num = WX2 * ((pt[j] + pt[j + 2]) + (pb[j] + pb[j + 2]))
                  + WC2 * (pt[j + 1] + pb[j + 1]);
        float den = WX2 * ((qt[j] + qt[j + 2]) + (qb[j] + qb[j + 2]))
                  + WC2 * (qt[j + 1] + qb[j + 1]);
        r[j] = __fdividef(num, (den == 0.0f) ? 1.0f : den);
    }

    *reinterpret_cast<float4*>(outO)     = make_float4(r[0], r[1], r[2], r[3]);
    *reinterpret_cast<float4*>(outO + 4) = make_float4(r[4], r[5], r[6], r[7]);
}

extern "C" void kernel_launch(void* const* d_in, const int* in_sizes, int n_in,
                              void* d_out, int out_size) {
    const float* x = (const float*)d_in[0];
    float* out = (float*)d_out;

    const int n = in_sizes[0];
    const int B = n / (H_DIM * W_DIM);

    min_reduce_kernel<<<NBLK_MIN, 256>>>(x, n / 4);

    dim3 grid(H_DIM, B);
    upsample_conv_kernel<<<grid, 256>>>(x, out);
}

// round 8
// speedup vs baseline: 1.8799x; 1.0303x over previous
#include <cuda_runtime.h>
#include <cuda_bf16.h>
#include <cstdint>

// Fixed problem shape: x [B=64, C=1, H=64, W=2048] f32
#define H_DIM 64
#define W_DIM 2048
#define NBLK_MIN 1024
#define R_STRIP 4

// 2*exp(-0.5*sqrt(2)) and 2*exp(-0.5)  (the 2x from the sigmoid folded into weights)
#define WX2 0.9861373827905206f
#define WC2 1.2130613194252668f

__device__ __align__(16) float g_blockmin[NBLK_MIN];

// ---------------- Pass 1: per-block minima (plain stores, no init needed) ---------
__global__ void __launch_bounds__(256) min_reduce_kernel(const float* __restrict__ x, int n4) {
    int gid = blockIdx.x * blockDim.x + threadIdx.x;
    int stride = gridDim.x * blockDim.x;
    float m = 3.4e38f;
    const float4* __restrict__ x4 = reinterpret_cast<const float4*>(x);
    for (int i = gid; i < n4; i += stride) {
        float4 v = __ldg(x4 + i);
        m = fminf(m, fminf(fminf(v.x, v.y), fminf(v.z, v.w)));
    }
    #pragma unroll
    for (int off = 16; off > 0; off >>= 1)
        m = fminf(m, __shfl_xor_sync(0xFFFFFFFFu, m, off));
    __shared__ float sm[8];
    int lane = threadIdx.x & 31;
    int wid = threadIdx.x >> 5;
    if (lane == 0) sm[wid] = m;
    __syncthreads();
    if (wid == 0) {
        m = (lane < 8) ? sm[lane] : 3.4e38f;
        #pragma unroll
        for (int off = 4; off > 0; off >>= 1)
            m = fminf(m, __shfl_xor_sync(0xFFFFFFFFu, m, off));
        if (lane == 0) g_blockmin[blockIdx.x] = m;
    }
}

// ---------------- Pass 2: strip kernel with row-stencil reuse ---------------------

__device__ __forceinline__ void load_row(const float* __restrict__ row, int c0, float v[10]) {
    float4 a = __ldg(reinterpret_cast<const float4*>(row + c0));
    float4 b = __ldg(reinterpret_cast<const float4*>(row + c0 + 4));
    v[1] = a.x; v[2] = a.y; v[3] = a.z; v[4] = a.w;
    v[5] = b.x; v[6] = b.y; v[7] = b.z; v[8] = b.w;
    v[0] = (c0 > 0) ? __ldg(row + c0 - 1) : 0.0f;
    v[9] = (c0 + 8 < W_DIM) ? __ldg(row + c0 + 8) : 0.0f;
}

__device__ __forceinline__ void store_row(float* __restrict__ o, const float v[10]) {
    *reinterpret_cast<float4*>(o)     = make_float4(v[1], v[2], v[3], v[4]);
    *reinterpret_cast<float4*>(o + 4) = make_float4(v[5], v[6], v[7], v[8]);
}

// per-row horizontal stencils: T over v*q, U over q  (weights fold the 2x)
__device__ __forceinline__ void stencil_row(const float v[10], float gmin,
                                            float T[8], float U[8]) {
    float q[10], p[10];
    #pragma unroll
    for (int i = 0; i < 10; i++) {
        float qi = (v[i] != 0.0f)
                 ? __fdividef(1.0f, 1.0f + __expf(v[i] - gmin)) : 0.0f;
        q[i] = qi;
        p[i] = v[i] * qi;
    }
    #pragma unroll
    for (int j = 0; j < 8; j++) {
        T[j] = WX2 * (p[j] + p[j + 2]) + WC2 * p[j + 1];
        U[j] = WX2 * (q[j] + q[j + 2]) + WC2 * q[j + 1];
    }
}

// grid: (H/R_STRIP, B), block 256. Thread owns 8 cols; block owns 4 pixel rows.
__global__ void __launch_bounds__(256) upsample_conv_kernel(const float* __restrict__ x,
                                                            float* __restrict__ out) {
    __shared__ float s_gmin;
    __shared__ float sm[8];
    const int tid = threadIdx.x;

    // Reduce the 1024 block-minima (L2-hot, 4KB) + padded zeros -> gmin
    {
        float4 v = *reinterpret_cast<const float4*>(g_blockmin + tid * 4);
        float m = fminf(fminf(v.x, v.y), fminf(v.z, v.w));
        #pragma unroll
        for (int off = 16; off > 0; off >>= 1)
            m = fminf(m, __shfl_xor_sync(0xFFFFFFFFu, m, off));
        int lane = tid & 31, wid = tid >> 5;
        if (lane == 0) sm[wid] = m;
        __syncthreads();
        if (tid == 0) {
            m = sm[0];
            #pragma unroll
            for (int i = 1; i < 8; i++) m = fminf(m, sm[i]);
            s_gmin = fminf(m, 0.0f);   // padded zeros participate in the global min
        }
        __syncthreads();
    }
    const float gmin = s_gmin;

    const int hp0 = blockIdx.x * R_STRIP;
    const int b = blockIdx.y;
    const int c0 = tid * 8;

    const float* __restrict__ base = x + (long)b * H_DIM * W_DIM;
    float* __restrict__ obase = out + (long)b * 2 * H_DIM * W_DIM;

    float v[10], Tp[8], Up[8];

    // row hp0: sigmoid once, emit its even-row copy
    load_row(base + (long)hp0 * W_DIM, c0, v);
    stencil_row(v, gmin, Tp, Up);
    store_row(obase + (long)(2 * hp0) * W_DIM + c0, v);

    #pragma unroll
    for (int r = 1; r <= R_STRIP; r++) {
        const int h = hp0 + r;
        if (h < H_DIM) {
            load_row(base + (long)h * W_DIM, c0, v);
            if (r < R_STRIP)    // row h's even copy belongs to this strip only for r<4
                store_row(obase + (long)(2 * h) * W_DIM + c0, v);

            float Tc[8], Uc[8];
            stencil_row(v, gmin, Tc, Uc);

            float rr[8];
            #pragma unroll
            for (int j = 0; j < 8; j++) {
                float den = Up[j] + Uc[j];
                rr[j] = __fdividef(Tp[j] + Tc[j], (den == 0.0f) ? 1.0f : den);
            }
            float* outO = obase + (long)(2 * h - 1) * W_DIM + c0;
            *reinterpret_cast<float4*>(outO)     = make_float4(rr[0], rr[1], rr[2], rr[3]);
            *reinterpret_cast<float4*>(outO + 4) = make_float4(rr[4], rr[5], rr[6], rr[7]);

            #pragma unroll
            for (int j = 0; j < 8; j++) { Tp[j] = Tc[j]; Up[j] = Uc[j]; }
        } else {
            // only the last strip (h == H): odd row 127 duplicates x's last row (L1-hot reload)
            const float* rowL = base + (long)(H_DIM - 1) * W_DIM + c0;
            float4 a = __ldg(reinterpret_cast<const float4*>(rowL));
            float4 bb = __ldg(reinterpret_cast<const float4*>(rowL + 4));
            float* outO = obase + (long)(2 * H_DIM - 1) * W_DIM + c0;
            *reinterpret_cast<float4*>(outO)     = a;
            *reinterpret_cast<float4*>(outO + 4) = bb;
        }
    }
}

extern "C" void kernel_launch(void* const* d_in, const int* in_sizes, int n_in,
                              void* d_out, int out_size) {
    const float* x = (const float*)d_in[0];
    float* out = (float*)d_out;

    const int n = in_sizes[0];
    const int B = n / (H_DIM * W_DIM);

    min_reduce_kernel<<<NBLK_MIN, 256>>>(x, n / 4);

    dim3 grid(H_DIM / R_STRIP, B);
    upsample_conv_kernel<<<grid, 256>>>(x, out);
}

// round 13
// speedup vs baseline: 2.1581x; 1.1480x over previous
#include <cuda_runtime.h>
#include <cuda_bf16.h>
#include <cstdint>

// Fixed problem shape: x [B=64, C=1, H=64, W=2048] f32
#define H_DIM 64
#define W_DIM 2048
#define NBLK_MIN 1024
#define R_STRIP 4
#define COLS 4          // columns per thread
#define TPB 256         // threads per block
#define WSPAN (TPB * COLS)   // 1024 cols per block
#define LOG2E 1.4426950408889634f

// 2*exp(-0.5*sqrt(2)) and 2*exp(-0.5)  (the 2x from the sigmoid folded into weights)
#define WX2 0.9861373827905206f
#define WC2 1.2130613194252668f

__device__ __align__(16) float g_blockmin[NBLK_MIN];

// ---------------- Pass 1: per-block minima (plain stores, no init needed) ---------
__global__ void __launch_bounds__(256) min_reduce_kernel(const float* __restrict__ x, int n4) {
    int gid = blockIdx.x * blockDim.x + threadIdx.x;
    int stride = gridDim.x * blockDim.x;
    float m = 3.4e38f;
    const float4* __restrict__ x4 = reinterpret_cast<const float4*>(x);
    for (int i = gid; i < n4; i += stride) {
        float4 v = __ldg(x4 + i);
        m = fminf(m, fminf(fminf(v.x, v.y), fminf(v.z, v.w)));
    }
    #pragma unroll
    for (int off = 16; off > 0; off >>= 1)
        m = fminf(m, __shfl_xor_sync(0xFFFFFFFFu, m, off));
    __shared__ float sm[8];
    int lane = threadIdx.x & 31;
    int wid = threadIdx.x >> 5;
    if (lane == 0) sm[wid] = m;
    __syncthreads();
    if (wid == 0) {
        m = (lane < 8) ? sm[lane] : 3.4e38f;
        #pragma unroll
        for (int off = 4; off > 0; off >>= 1)
            m = fminf(m, __shfl_xor_sync(0xFFFFFFFFu, m, off));
        if (lane == 0) g_blockmin[blockIdx.x] = m;
    }
}

// ---------------- Pass 2: strip kernel with row-stencil reuse ---------------------

__device__ __forceinline__ float ex2f(float x) {
    float r;
    asm("ex2.approx.f32 %0, %1;" : "=f"(r) : "f"(x));
    return r;
}

__device__ __forceinline__ void load_row(const float* __restrict__ row, int c0, float v[COLS + 2]) {
    float4 a = __ldg(reinterpret_cast<const float4*>(row + c0));
    v[1] = a.x; v[2] = a.y; v[3] = a.z; v[4] = a.w;
    v[0] = (c0 > 0) ? __ldg(row + c0 - 1) : 0.0f;
    v[5] = (c0 + COLS < W_DIM) ? __ldg(row + c0 + COLS) : 0.0f;
}

__device__ __forceinline__ void store_row(float* __restrict__ o, const float v[COLS + 2]) {
    *reinterpret_cast<float4*>(o) = make_float4(v[1], v[2], v[3], v[4]);
}

// per-row horizontal stencils: T over v*q, U over q  (weights fold the 2x)
__device__ __forceinline__ void stencil_row(const float v[COLS + 2], float ngl,
                                            float T[COLS], float U[COLS]) {
    float q[COLS + 2], p[COLS + 2];
    #pragma unroll
    for (int i = 0; i < COLS + 2; i++) {
        // exp(v - gmin) = 2^(v*log2e - gmin*log2e);  ngl = -gmin*log2e
        float e = ex2f(fmaf(v[i], LOG2E, ngl));
        float qi = (v[i] != 0.0f) ? __fdividef(1.0f, 1.0f + e) : 0.0f;
        q[i] = qi;
        p[i] = v[i] * qi;
    }
    #pragma unroll
    for (int j = 0; j < COLS; j++) {
        T[j] = WX2 * (p[j] + p[j + 2]) + WC2 * p[j + 1];
        U[j] = WX2 * (q[j] + q[j + 2]) + WC2 * q[j + 1];
    }
}

// grid: (W/WSPAN, H/R_STRIP, B), block 256. Thread owns 4 cols; block owns 4 pixel rows.
__global__ void __launch_bounds__(256, 6) upsample_conv_kernel(const float* __restrict__ x,
                                                               float* __restrict__ out) {
    __shared__ float s_ngl;
    __shared__ float sm[8];
    const int tid = threadIdx.x;

    // Reduce the 1024 block-minima (L2-hot, 4KB) + padded zeros -> gmin
    {
        float4 v = *reinterpret_cast<const float4*>(g_blockmin + tid * 4);
        float m = fminf(fminf(v.x, v.y), fminf(v.z, v.w));
        #pragma unroll
        for (int off = 16; off > 0; off >>= 1)
            m = fminf(m, __shfl_xor_sync(0xFFFFFFFFu, m, off));
        int lane = tid & 31, wid = tid >> 5;
        if (lane == 0) sm[wid] = m;
        __syncthreads();
        if (tid == 0) {
            m = sm[0];
            #pragma unroll
            for (int i = 1; i < 8; i++) m = fminf(m, sm[i]);
            // padded zeros participate in the global min; store -gmin*log2e
            s_ngl = -fminf(m, 0.0f) * LOG2E;
        }
        __syncthreads();
    }
    const float ngl = s_ngl;

    const int c0 = blockIdx.x * WSPAN + tid * COLS;
    const int hp0 = blockIdx.y * R_STRIP;
    const int b = blockIdx.z;

    const float* __restrict__ base = x + (long)b * H_DIM * W_DIM;
    float* __restrict__ obase = out + (long)b * 2 * H_DIM * W_DIM;

    float v[COLS + 2], Tp[COLS], Up[COLS];

    // row hp0: sigmoid once, emit its even-row copy
    load_row(base + (long)hp0 * W_DIM, c0, v);
    stencil_row(v, ngl, Tp, Up);
    store_row(obase + (long)(2 * hp0) * W_DIM + c0, v);

    #pragma unroll
    for (int r = 1; r <= R_STRIP; r++) {
        const int h = hp0 + r;
        if (h < H_DIM) {
            load_row(base + (long)h * W_DIM, c0, v);
            if (r < R_STRIP)    // row h's even copy belongs to this strip only for r<R_STRIP
                store_row(obase + (long)(2 * h) * W_DIM + c0, v);

            float Tc[COLS], Uc[COLS];
            stencil_row(v, ngl, Tc, Uc);

            float rr[COLS];
            #pragma unroll
            for (int j = 0; j < COLS; j++) {
                float den = Up[j] + Uc[j];
                rr[j] = __fdividef(Tp[j] + Tc[j], (den == 0.0f) ? 1.0f : den);
            }
            float* outO = obase + (long)(2 * h - 1) * W_DIM + c0;
            *reinterpret_cast<float4*>(outO) = make_float4(rr[0], rr[1], rr[2], rr[3]);

            #pragma unroll
            for (int j = 0; j < COLS; j++) { Tp[j] = Tc[j]; Up[j] = Uc[j]; }
        } else {
            // only the last strip (h == H): odd row 127 duplicates x's last row (L1-hot reload)
            const float* rowL = base + (long)(H_DIM - 1) * W_DIM + c0;
            float4 a = __ldg(reinterpret_cast<const float4*>(rowL));
            float* outO = obase + (long)(2 * H_DIM - 1) * W_DIM + c0;
            *reinterpret_cast<float4*>(outO) = a;
        }
    }
}

extern "C" void kernel_launch(void* const* d_in, const int* in_sizes, int n_in,
                              void* d_out, int out_size) {
    const float* x = (const float*)d_in[0];
    float* out = (float*)d_out;

    const int n = in_sizes[0];
    const int B = n / (H_DIM * W_DIM);

    min_reduce_kernel<<<NBLK_MIN, 256>>>(x, n / 4);

    dim3 grid(W_DIM / WSPAN, H_DIM / R_STRIP, B);
    upsample_conv_kernel<<<grid, TPB>>>(x, out);
}